// round 14
// baseline (speedup 1.0000x reference)
#include <cuda_runtime.h>
#include <cuda_fp16.h>
#include <math.h>
#include <stdint.h>

#define BATCH 32
#define IMG 224
#define PSZ 16
#define SGRID 14
#define NPATCH 196
#define NTOK 197
#define CDIM 768
#define HEADS 12
#define HDIM 64
#define DEPTH 12
#define HID 3072
#define NCLS 1000
#define NCURVES 6
#define ROWS (BATCH*NTOK)     /* 6304 */
#define PROWS (BATCH*NPATCH)  /* 6272 */
#define KSTRIDE 68

#define QKV_T   (2304*768)
#define PROJ_T  (768*768)
#define FC1_T   (768*3072)
#define FC2_T   (3072*768)
#define OFF_QKV   0
#define OFF_PROJ  (OFF_QKV  + 12*QKV_T)
#define OFF_FC1   (OFF_PROJ + 12*PROJ_T)
#define OFF_FC2   (OFF_FC1  + 12*FC1_T)
#define OFF_PATCH (OFF_FC2  + 12*FC2_T)
#define WTOT      (OFF_PATCH + 768*768)
#define MSZ (HEADS*NTOK*NTOK)
#define NN (NTOK*NTOK)

// ---------------- device scratch ----------------
__device__ __half g_wh[WTOT];
__device__ __half g_hh[ROWS*CDIM],  g_hl[ROWS*CDIM];
__device__ __half g_oh[ROWS*CDIM],  g_ol[ROWS*CDIM];
__device__ __half g_h2h[ROWS*HID],  g_h2l[ROWS*HID];
__device__ __half g_pah[PROWS*CDIM],g_pal[PROWS*CDIM];
__device__ float g_x[ROWS*CDIM];
__device__ float g_qkv[ROWS*3*CDIM];
__device__ float g_M[DEPTH*MSZ];
__device__ float g_pt[PROWS*CDIM];
__device__ float g_cls[BATCH*CDIM];

// ---------------- helpers ----------------
__device__ __forceinline__ float warpMax(float v){
#pragma unroll
  for (int o=16;o;o>>=1) v = fmaxf(v, __shfl_xor_sync(0xffffffffu, v, o));
  return v;
}
__device__ __forceinline__ float warpSum(float v){
#pragma unroll
  for (int o=16;o;o>>=1) v += __shfl_xor_sync(0xffffffffu, v, o);
  return v;
}
__device__ __forceinline__ uint32_t cvta_s(const void* p){
  return (uint32_t)__cvta_generic_to_shared(p);
}
__device__ __forceinline__ void mma16816(float* c, const uint32_t* a, const uint32_t* b){
  asm volatile(
    "mma.sync.aligned.m16n8k16.row.col.f32.f16.f16.f32 "
    "{%0,%1,%2,%3},{%4,%5,%6,%7},{%8,%9},{%0,%1,%2,%3};"
    : "+f"(c[0]), "+f"(c[1]), "+f"(c[2]), "+f"(c[3])
    : "r"(a[0]), "r"(a[1]), "r"(a[2]), "r"(a[3]), "r"(b[0]), "r"(b[1]));
}
__device__ __forceinline__ void ldm_x4(uint32_t* r, uint32_t addr){
  asm volatile("ldmatrix.sync.aligned.m8n8.x4.shared.b16 {%0,%1,%2,%3},[%4];"
    : "=r"(r[0]), "=r"(r[1]), "=r"(r[2]), "=r"(r[3]) : "r"(addr));
}
__device__ __forceinline__ void cp_async16(uint32_t dst, const void* src, int szbytes){
  asm volatile("cp.async.cg.shared.global [%0], [%1], 16, %2;"
               :: "r"(dst), "l"(src), "r"(szbytes) : "memory");
}
#define CP_COMMIT() asm volatile("cp.async.commit_group;" ::: "memory")
#define CP_WAIT(n)  asm volatile("cp.async.wait_group %0;" :: "n"(n) : "memory")

__device__ __forceinline__ uint32_t swz(int row, int ch){
  return (uint32_t)row*64u + (uint32_t)((ch ^ ((row>>1)&3)) << 4);
}
__device__ __forceinline__ void split2h(float v, __half* hh, __half* hl){
  __half h = __float2half_rn(v);
  *hh = h;
  *hl = __float2half_rn(v - __half2float(h));
}

// ---------------- weight preprocessing (batched over layers) ----------------
__global__ void tsplit_kernel(const float* __restrict__ W0, __half* __restrict__ Th0,
                              int K, int N){
  __shared__ float t[32][33];
  const float* W = W0 + (size_t)blockIdx.z * K * N;
  __half* Th = Th0 + (size_t)blockIdx.z * K * N;
  int k0 = blockIdx.y*32, n0 = blockIdx.x*32;
  int tx = threadIdx.x, ty = threadIdx.y;
#pragma unroll
  for (int i=0;i<32;i+=8){
    int k = k0+ty+i, n = n0+tx;
    t[ty+i][tx] = (k<K && n<N) ? W[(size_t)k*N+n] : 0.0f;
  }
  __syncthreads();
#pragma unroll
  for (int i=0;i<32;i+=8){
    int n = n0+ty+i, k = k0+tx;
    if (n<N && k<K) Th[(size_t)n*K+k] = __float2half_rn(t[tx][ty+i]);
  }
}

__global__ void split_pw_kernel(const float* __restrict__ W, __half* __restrict__ Th){
  int idx = blockIdx.x*256 + threadIdx.x;
  if (idx >= CDIM*CDIM) return;
  Th[idx] = __float2half_rn(W[idx]);
}

// ---------------- patch embed ----------------
__global__ void im2col_kernel(const float* __restrict__ img,
                              __half* __restrict__ ph, __half* __restrict__ pl){
  int idx = blockIdx.x*256 + threadIdx.x;
  if (idx >= PROWS*CDIM) return;
  int row = idx / CDIM, k = idx % CDIM;
  int b = row / NPATCH, p = row % NPATCH;
  int py = p / SGRID, px = p % SGRID;
  int ci = k / (PSZ*PSZ), rr = k % (PSZ*PSZ);
  int phh = rr / PSZ, pww = rr % PSZ;
  float v = img[ ((size_t)(b*3 + ci)*IMG + (py*PSZ + phh))*IMG + (px*PSZ + pww) ];
  split2h(v, &ph[idx], &pl[idx]);
}

__global__ void assemble_ln_kernel(const float* __restrict__ pt, const float* __restrict__ cls_tok,
                                   const float* __restrict__ pos, const float* __restrict__ pbias,
                                   const float* __restrict__ w, const float* __restrict__ b,
                                   float* __restrict__ x,
                                   __half* __restrict__ oh, __half* __restrict__ ol){
  __shared__ float redS[8], redQ[8];
  __shared__ float s_mean, s_inv;
  int r = blockIdx.x;
  int bb = r / NTOK, n = r % NTOK;
  int tid = threadIdx.x, lane = tid & 31, wid = tid >> 5;

  float vv[3];
#pragma unroll
  for (int e = 0; e < 3; ++e){
    int c = tid + e*256;
    float v;
    if (n == 0) v = cls_tok[c];
    else        v = pt[(size_t)(bb*NPATCH + (n-1))*CDIM + c] + pbias[c];
    v += pos[n*CDIM + c];
    vv[e] = v;
    x[(size_t)r*CDIM + c] = v;
  }
  float s = vv[0]+vv[1]+vv[2];
  float q = vv[0]*vv[0]+vv[1]*vv[1]+vv[2]*vv[2];
  s = warpSum(s); q = warpSum(q);
  if (lane == 0){ redS[wid] = s; redQ[wid] = q; }
  __syncthreads();
  if (tid == 0){
    float ts = 0.0f, tq = 0.0f;
#pragma unroll
    for (int i = 0; i < 8; ++i){ ts += redS[i]; tq += redQ[i]; }
    float mean = ts * (1.0f/CDIM);
    s_mean = mean;
    s_inv = rsqrtf(tq * (1.0f/CDIM) - mean*mean + 1e-5f);
  }
  __syncthreads();
  float mean = s_mean, inv = s_inv;
#pragma unroll
  for (int e = 0; e < 3; ++e){
    int c = tid + e*256;
    float y = (vv[e] - mean) * inv * w[c] + b[c];
    split2h(y, &oh[(size_t)r*CDIM + c], &ol[(size_t)r*CDIM + c]);
  }
}

// ---------------- M via lookup tables, D fused inline ----------------
// blockIdx.z = layer. table[h][c][d] = sigmoid(ai[layer,c,h])^d.
__global__ void compute_M_kernel(const float* __restrict__ ai, const int* __restrict__ ci,
                                 float* __restrict__ M12){
  __shared__ float table[HEADS][NCURVES][196];
  __shared__ int cis[NCURVES*NPATCH];
  int tid = threadIdx.x;
  int layer = blockIdx.z;
  for (int e = tid; e < NCURVES*NPATCH; e += 256) cis[e] = ci[e];
  for (int e = tid; e < HEADS*NCURVES*196; e += 256){
    int h = e / (NCURVES*196);
    int rem = e % (NCURVES*196);
    int c = rem / 196, dd = rem % 196;
    float a = ai[layer*NCURVES*HEADS + c*HEADS + h];
    float sig = 1.0f/(1.0f + expf(-a));
    table[h][c][dd] = exp2f((float)dd * log2f(sig));
  }
  __syncthreads();

  int idx = blockIdx.x*256 + tid;
  if (idx >= NN) return;
  int i = idx / NTOK, j = idx % NTOK;
  float* Mout = M12 + (size_t)layer*MSZ + idx;
  if (i == 0 || j == 0){
#pragma unroll
    for (int h = 0; h < HEADS; ++h)
      Mout[(size_t)h*NN] = 1.0f;
  } else {
    int dv[NCURVES];
#pragma unroll
    for (int c = 0; c < NCURVES; ++c){
      int d = cis[c*NPATCH + (i-1)] - cis[c*NPATCH + (j-1)];
      dv[c] = d < 0 ? -d : d;
    }
#pragma unroll
    for (int h = 0; h < HEADS; ++h){
      float acc = 0.0f;
#pragma unroll
      for (int c = 0; c < NCURVES; ++c)
        acc += table[h][c][dv[c]];
      Mout[(size_t)h*NN] = acc * (1.0f/6.0f);
    }
  }
}

// ---------------- layernorm ----------------
template<int PAIR>
__global__ void layernorm_kernel(const float* __restrict__ in, long in_stride,
                                 const float* __restrict__ w, const float* __restrict__ b,
                                 float* __restrict__ outf,
                                 __half* __restrict__ oh, __half* __restrict__ ol){
  __shared__ float redS[8], redQ[8];
  __shared__ float s_mean, s_inv;
  int r = blockIdx.x;
  const float* xr = in + (long)r * in_stride;
  int tid = threadIdx.x, lane = tid & 31, wid = tid >> 5;

  float v0 = xr[tid], v1 = xr[tid+256], v2 = xr[tid+512];
  float s = v0 + v1 + v2;
  float q = v0*v0 + v1*v1 + v2*v2;
  s = warpSum(s); q = warpSum(q);
  if (lane == 0){ redS[wid] = s; redQ[wid] = q; }
  __syncthreads();
  if (tid == 0){
    float ts = 0.0f, tq = 0.0f;
#pragma unroll
    for (int i = 0; i < 8; ++i){ ts += redS[i]; tq += redQ[i]; }
    float mean = ts * (1.0f/CDIM);
    s_mean = mean;
    s_inv = rsqrtf(tq * (1.0f/CDIM) - mean*mean + 1e-5f);
  }
  __syncthreads();
  float mean = s_mean, inv = s_inv;
#pragma unroll
  for (int e = 0; e < 3; ++e){
    int c = tid + e*256;
    float xv = (e==0) ? v0 : (e==1) ? v1 : v2;
    float y = (xv - mean) * inv * w[c] + b[c];
    if (PAIR){
      split2h(y, &oh[(size_t)r*CDIM + c], &ol[(size_t)r*CDIM + c]);
    } else {
      outf[(size_t)r*CDIM + c] = y;
    }
  }
}

// ---------------- split-fp16 MMA GEMM: 128x128 tile, 3-stage ----------------
// EPI 0: fp32 store. 2: +bias +res -> fp32 store. 3: +bias, GELU -> fp16 pair.
// EPI 4: split-K partial -> atomicAdd into Cf (res pre-resident); bias by z==0.
template<int EPI>
__global__ void __launch_bounds__(256, 2)
mma_gemm_kernel(const __half* __restrict__ Ah_, const __half* __restrict__ Al_,
                const __half* __restrict__ Bh_,
                const float* __restrict__ bias, const float* __restrict__ res,
                float* __restrict__ Cf, __half* __restrict__ Ch, __half* __restrict__ Cl,
                int M, int N, int K, int Kchunk){
  extern __shared__ __align__(16) char dsm[];
  uint32_t sb = cvta_s(dsm);  // [3 stages][AH 8K | AL 8K | BH 8K]

  int tid = threadIdx.x, wid = tid >> 5, lane = tid & 31;
  int m0 = blockIdx.y * 128, n0 = blockIdx.x * 128;
  int kbase = blockIdx.z * Kchunk;
  int warp_m = wid >> 2, warp_n = wid & 3;

  float acc[4][4][4];
#pragma unroll
  for (int a=0;a<4;++a)
#pragma unroll
    for (int b=0;b<4;++b)
#pragma unroll
      for (int c=0;c<4;++c) acc[a][b][c] = 0.0f;

  auto load_stage = [&](int it, int s){
    int k0 = kbase + it * 32;
    uint32_t st = sb + (uint32_t)s*24576u;
#pragma unroll
    for (int i = 0; i < 2; ++i){
      int c = i*256 + tid;
      int row = c >> 2, ch = c & 3;
      int gr = m0 + row;
      int ok = gr < M;
      cp_async16(st + swz(row,ch), Ah_ + (size_t)(ok?gr:0)*K + k0 + ch*8, ok?16:0);
    }
#pragma unroll
    for (int i = 0; i < 2; ++i){
      int c = i*256 + tid;
      int row = c >> 2, ch = c & 3;
      int gr = m0 + row;
      int ok = gr < M;
      cp_async16(st + 8192u + swz(row,ch), Al_ + (size_t)(ok?gr:0)*K + k0 + ch*8, ok?16:0);
    }
#pragma unroll
    for (int i = 0; i < 2; ++i){
      int c = i*256 + tid;
      int row = c >> 2, ch = c & 3;
      cp_async16(st + 16384u + swz(row,ch), Bh_ + (size_t)(n0+row)*K + k0 + ch*8, 16);
    }
  };

  int niter = Kchunk >> 5;
  load_stage(0, 0); CP_COMMIT();
  load_stage(1, 1); CP_COMMIT();

  for (int it = 0; it < niter; ++it){
    CP_WAIT(1);
    __syncthreads();
    if (it + 2 < niter) load_stage(it + 2, (it + 2) % 3);
    CP_COMMIT();

    int s = it % 3;
    uint32_t Abh = sb + (uint32_t)s*24576u;
    uint32_t Abl = Abh + 8192u;
    uint32_t Bbh = Abh + 16384u;

#pragma unroll
    for (int k16 = 0; k16 < 2; ++k16){
      uint32_t bf[2][4];
#pragma unroll
      for (int g = 0; g < 2; ++g){
        int brow = warp_n*32 + g*16 + (lane & 7) + ((lane >> 4) << 3);
        int bch = k16*2 + ((lane >> 3) & 1);
        ldm_x4(bf[g], Bbh + swz(brow, bch));
      }
      int arow_b = warp_m*64 + (lane & 15);
      int ach = k16*2 + (lane >> 4);
#pragma unroll
      for (int mt = 0; mt < 4; ++mt){
        uint32_t af[4];
        uint32_t aoff = swz(arow_b + mt*16, ach);
        ldm_x4(af, Abh + aoff);
        mma16816(acc[mt][0], af, bf[0]+0);
        mma16816(acc[mt][1], af, bf[0]+2);
        mma16816(acc[mt][2], af, bf[1]+0);
        mma16816(acc[mt][3], af, bf[1]+2);
        ldm_x4(af, Abl + aoff);
        mma16816(acc[mt][0], af, bf[0]+0);
        mma16816(acc[mt][1], af, bf[0]+2);
        mma16816(acc[mt][2], af, bf[1]+0);
        mma16816(acc[mt][3], af, bf[1]+2);
      }
    }
  }

  // epilogue
#pragma unroll
  for (int mt = 0; mt < 4; ++mt){
#pragma unroll
    for (int nt = 0; nt < 4; ++nt){
#pragma unroll
      for (int half = 0; half < 2; ++half){
        int gm = m0 + warp_m*64 + mt*16 + (lane >> 2) + half*8;
        if (gm >= M) continue;
#pragma unroll
        for (int e = 0; e < 2; ++e){
          int gn = n0 + warp_n*32 + nt*8 + 2*(lane & 3) + e;
          float v = acc[mt][nt][half*2 + e];
          if (EPI == 0){
            Cf[(size_t)gm*N + gn] = v;
          } else if (EPI == 2){
            v += bias[gn] + res[(size_t)gm*N + gn];
            Cf[(size_t)gm*N + gn] = v;
          } else if (EPI == 4){
            if (blockIdx.z == 0) v += bias[gn];
            atomicAdd(&Cf[(size_t)gm*N + gn], v);
          } else {
            v += bias[gn];
            float g = 0.5f * v * (1.0f + erff(v * 0.7071067811865475f));
            split2h(g, &Ch[(size_t)gm*N + gn], &Cl[(size_t)gm*N + gn]);
          }
        }
      }
    }
  }
}

// ---------------- attention: warp-per-row, 8 warps, ILP'd PV loop ----------------
__global__ void __launch_bounds__(256)
attention_kernel(const float* __restrict__ qkv, const float* __restrict__ M,
                 __half* __restrict__ oh, __half* __restrict__ ol){
  extern __shared__ float sm[];
  float* ks = sm;
  float* vs = ks + NTOK*KSTRIDE;
  float* qs = vs + NTOK*KSTRIDE;
  float* ps = qs + 8*68;

  int bh = blockIdx.x;
  int b = bh / HEADS, h = bh % HEADS;
  int tid = threadIdx.x, lane = tid & 31, wid = tid >> 5;
  const float scale = 0.125f;

  size_t base = (size_t)b * NTOK * 3 * CDIM;
  for (int idx = tid; idx < NTOK*16; idx += 256){
    int j = idx >> 4, d4 = idx & 15;
    float4 kv = *(const float4*)(qkv + base + (size_t)j*3*CDIM + CDIM   + h*HDIM + d4*4);
    float4 vv = *(const float4*)(qkv + base + (size_t)j*3*CDIM + 2*CDIM + h*HDIM + d4*4);
    *(float4*)(ks + j*KSTRIDE + d4*4) = kv;
    *(float4*)(vs + j*KSTRIDE + d4*4) = vv;
  }
  __syncthreads();

  const float* Mh = M + (size_t)h * NN;
  float* qw = qs + wid*68;
  float* pw = ps + wid*224;

  for (int i = wid; i < NTOK; i += 8){
    if (lane < 16)
      *(float4*)(qw + lane*4) = *(const float4*)(qkv + base + (size_t)i*3*CDIM + h*HDIM + lane*4);
    __syncwarp();

    float sj[7];
    float mx = -1e30f;
#pragma unroll
    for (int jj = 0; jj < 7; ++jj){
      int j = lane + jj*32;
      float acc = -1e30f;
      if (j < NTOK){
        const float4* k4 = (const float4*)(ks + j*KSTRIDE);
        const float4* q4 = (const float4*)qw;
        float a = 0.0f;
#pragma unroll
        for (int d4 = 0; d4 < 16; ++d4){
          float4 kv = k4[d4], qv = q4[d4];
          a += qv.x*kv.x + qv.y*kv.y + qv.z*kv.z + qv.w*kv.w;
        }
        acc = a * scale * Mh[(size_t)i*NTOK + j];
      }
      sj[jj] = acc;
      mx = fmaxf(mx, acc);
    }
    mx = warpMax(mx);
    float sum = 0.0f;
#pragma unroll
    for (int jj = 0; jj < 7; ++jj){
      int j = lane + jj*32;
      float p = (j < NTOK) ? __expf(sj[jj] - mx) : 0.0f;
      pw[j] = p;
      sum += p;
    }
    sum = warpSum(sum);
    float rinv = 1.0f / sum;
    __syncwarp();

    // PV: 4 independent accumulator pairs to break the FMA RAW chain
    float a0 = 0.f, a1 = 0.f, b0 = 0.f, b1 = 0.f;
    float c0 = 0.f, c1 = 0.f, d0 = 0.f, d1 = 0.f;
    int j = 0;
    for (; j + 4 <= 196; j += 4){
      float p0 = pw[j], p1 = pw[j+1], p2 = pw[j+2], p3 = pw[j+3];
      float2 v0 = *(const float2*)(vs + (j  )*KSTRIDE + lane*2);
      float2 v1 = *(const float2*)(vs + (j+1)*KSTRIDE + lane*2);
      float2 v2 = *(const float2*)(vs + (j+2)*KSTRIDE + lane*2);
      float2 v3 = *(const float2*)(vs + (j+3)*KSTRIDE + lane*2);
      a0 += p0*v0.x; a1 += p0*v0.y;
      b0 += p1*v1.x; b1 += p1*v1.y;
      c0 += p2*v2.x; c1 += p2*v2.y;
      d0 += p3*v3.x; d1 += p3*v3.y;
    }
    { // j = 196 tail
      float p = pw[196];
      float2 vv = *(const float2*)(vs + 196*KSTRIDE + lane*2);
      a0 += p*vv.x; a1 += p*vv.y;
    }
    float o0 = ((a0 + b0) + (c0 + d0)) * rinv;
    float o1 = ((a1 + b1) + (c1 + d1)) * rinv;
    size_t oidx = ((size_t)(b*NTOK + i))*CDIM + h*HDIM + lane*2;
    split2h(o0, &oh[oidx],   &ol[oidx]);
    split2h(o1, &oh[oidx+1], &ol[oidx+1]);
    __syncwarp();
  }
}

// ---------------- classifier head ----------------
__global__ void head_kernel(const float* __restrict__ cls, const float* __restrict__ W,
                            const float* __restrict__ bias, float* __restrict__ out){
  __shared__ float cs[CDIM];
  int b = blockIdx.y;
  int n = blockIdx.x*256 + threadIdx.x;
  for (int k = threadIdx.x; k < CDIM; k += 256) cs[k] = cls[b*CDIM + k];
  __syncthreads();
  if (n < NCLS){
    float acc = bias[n];
#pragma unroll 4
    for (int k = 0; k < CDIM; ++k)
      acc += cs[k] * W[(size_t)k*NCLS + n];
    out[b*NCLS + n] = acc;
  }
}

// ---------------- launcher ----------------
extern "C" void kernel_launch(void* const* d_in, const int* in_sizes, int n_in,
                              void* d_out, int out_size){
  (void)in_sizes; (void)n_in; (void)out_size;
  const float* images  = (const float*)d_in[0];
  const float* patch_w = (const float*)d_in[1];
  const float* patch_b = (const float*)d_in[2];
  const float* cls_tok = (const float*)d_in[3];
  const float* pos_emb = (const float*)d_in[4];
  const float* ln1_w   = (const float*)d_in[5];
  const float* ln1_b   = (const float*)d_in[6];
  const float* qkv_w   = (const float*)d_in[7];
  const float* proj_w  = (const float*)d_in[8];
  const float* proj_b  = (const float*)d_in[9];
  const float* ai      = (const float*)d_in[10];
  const float* ln2_w   = (const float*)d_in[11];
  const float* ln2_b   = (const float*)d_in[12];
  const float* fc1_w   = (const float*)d_in[13];
  const float* fc1_b   = (const float*)d_in[14];
  const float* fc2_w   = (const float*)d_in[15];
  const float* fc2_b   = (const float*)d_in[16];
  const float* norm_w  = (const float*)d_in[17];
  const float* norm_b  = (const float*)d_in[18];
  const float* head_w  = (const float*)d_in[19];
  const float* head_b  = (const float*)d_in[20];
  const int*   curve   = (const int*)d_in[21];
  float* out = (float*)d_out;

  __half *wh,*hh,*hl,*oh,*ol,*h2h,*h2l,*pah,*pal;
  float *x,*qkvb,*Mb,*pt,*cls;
  cudaGetSymbolAddress((void**)&wh,  g_wh);
  cudaGetSymbolAddress((void**)&hh,  g_hh);
  cudaGetSymbolAddress((void**)&hl,  g_hl);
  cudaGetSymbolAddress((void**)&oh,  g_oh);
  cudaGetSymbolAddress((void**)&ol,  g_ol);
  cudaGetSymbolAddress((void**)&h2h, g_h2h);
  cudaGetSymbolAddress((void**)&h2l, g_h2l);
  cudaGetSymbolAddress((void**)&pah, g_pah);
  cudaGetSymbolAddress((void**)&pal, g_pal);
  cudaGetSymbolAddress((void**)&x,   g_x);
  cudaGetSymbolAddress((void**)&qkvb,g_qkv);
  cudaGetSymbolAddress((void**)&Mb,  g_M);
  cudaGetSymbolAddress((void**)&pt,  g_pt);
  cudaGetSymbolAddress((void**)&cls, g_cls);

  const int attSmem = (2*NTOK*KSTRIDE + 8*68 + 8*224) * (int)sizeof(float);
  cudaFuncSetAttribute(attention_kernel, cudaFuncAttributeMaxDynamicSharedMemorySize, attSmem);
  const int gemmSmem = 73728;  // 3 stages x 24KB
  cudaFuncSetAttribute(mma_gemm_kernel<0>, cudaFuncAttributeMaxDynamicSharedMemorySize, gemmSmem);
  cudaFuncSetAttribute(mma_gemm_kernel<2>, cudaFuncAttributeMaxDynamicSharedMemorySize, gemmSmem);
  cudaFuncSetAttribute(mma_gemm_kernel<3>, cudaFuncAttributeMaxDynamicSharedMemorySize, gemmSmem);
  cudaFuncSetAttribute(mma_gemm_kernel<4>, cudaFuncAttributeMaxDynamicSharedMemorySize, gemmSmem);

  dim3 tb(32, 8);
  const int mt = (ROWS + 127)/128;   // 50
  const int pmt = (PROWS + 127)/128; // 49

  // ---- ordered so launch #6 (ncu -s 5 -c 1) is the layer-0 QKV GEMM ----
  im2col_kernel<<<(PROWS*CDIM+255)/256, 256>>>(images, pah, pal);                         // 1
  split_pw_kernel<<<(CDIM*CDIM+255)/256, 256>>>(patch_w, wh + OFF_PATCH);                 // 2
  tsplit_kernel<<<dim3(2304/32, 768/32, DEPTH), tb>>>(qkv_w,  wh + OFF_QKV,  768, 2304);  // 3
  mma_gemm_kernel<0><<<dim3(768/128, pmt), 256, gemmSmem>>>(                              // 4
      pah, pal, wh + OFF_PATCH,
      nullptr, nullptr, pt, nullptr, nullptr, PROWS, 768, 768, 768);
  assemble_ln_kernel<<<ROWS, 256>>>(pt, cls_tok, pos_emb, patch_b, ln1_w, ln1_b, x, hh, hl); // 5
  mma_gemm_kernel<0><<<dim3(2304/128, mt), 256, gemmSmem>>>(                              // 6 <- profiled
      hh, hl, wh + OFF_QKV,
      nullptr, nullptr, qkvb, nullptr, nullptr, ROWS, 2304, 768, 768);
  tsplit_kernel<<<dim3(768/32,  768/32, DEPTH), tb>>>(proj_w, wh + OFF_PROJ, 768, 768);   // 7
  tsplit_kernel<<<dim3(3072/32, 768/32, DEPTH), tb>>>(fc1_w,  wh + OFF_FC1,  768, 3072);  // 8
  tsplit_kernel<<<dim3(768/32, 3072/32, DEPTH), tb>>>(fc2_w,  wh + OFF_FC2,  3072, 768);  // 9
  compute_M_kernel<<<dim3((NN+255)/256, 1, DEPTH), 256>>>(ai, curve, Mb);                 // 10

  for (int d = 0; d < DEPTH; ++d){
    if (d > 0){
      layernorm_kernel<1><<<ROWS, 256>>>(x, CDIM, ln1_w + d*CDIM, ln1_b + d*CDIM, nullptr, hh, hl);
      mma_gemm_kernel<0><<<dim3(2304/128, mt), 256, gemmSmem>>>(
          hh, hl, wh + OFF_QKV + (size_t)d*QKV_T,
          nullptr, nullptr, qkvb, nullptr, nullptr, ROWS, 2304, 768, 768);
    }
    attention_kernel<<<BATCH*HEADS, 256, attSmem>>>(qkvb, Mb + (size_t)d*MSZ, oh, ol);
    mma_gemm_kernel<4><<<dim3(768/128, mt, 2), 256, gemmSmem>>>(
        oh, ol, wh + OFF_PROJ + (size_t)d*PROJ_T,
        proj_b + d*CDIM, nullptr, x, nullptr, nullptr, ROWS, 768, 768, 384);
    layernorm_kernel<1><<<ROWS, 256>>>(x, CDIM, ln2_w + d*CDIM, ln2_b + d*CDIM, nullptr, hh, hl);
    mma_gemm_kernel<3><<<dim3(3072/128, mt), 256, gemmSmem>>>(
        hh, hl, wh + OFF_FC1 + (size_t)d*FC1_T,
        fc1_b + d*HID, nullptr, nullptr, h2h, h2l, ROWS, 3072, 768, 768);
    mma_gemm_kernel<4><<<dim3(768/128, mt, 4), 256, gemmSmem>>>(
        h2h, h2l, wh + OFF_FC2 + (size_t)d*FC2_T,
        fc2_b + d*CDIM, nullptr, x, nullptr, nullptr, ROWS, 768, 3072, 768);
  }

  layernorm_kernel<0><<<BATCH, 256>>>(x, (long)NTOK*CDIM, norm_w, norm_b, cls, nullptr, nullptr);
  head_kernel<<<dim3(4, BATCH), 256>>>(cls, head_w, head_b, out);
}

// round 15
// speedup vs baseline: 1.0019x; 1.0019x over previous
#include <cuda_runtime.h>
#include <cuda_fp16.h>
#include <math.h>
#include <stdint.h>

#define BATCH 32
#define IMG 224
#define PSZ 16
#define SGRID 14
#define NPATCH 196
#define NTOK 197
#define CDIM 768
#define HEADS 12
#define HDIM 64
#define DEPTH 12
#define HID 3072
#define NCLS 1000
#define NCURVES 6
#define ROWS (BATCH*NTOK)     /* 6304 */
#define PROWS (BATCH*NPATCH)  /* 6272 */
#define KSTRIDE 68

#define QKV_T   (2304*768)
#define PROJ_T  (768*768)
#define FC1_T   (768*3072)
#define FC2_T   (3072*768)
#define OFF_QKV   0
#define OFF_PROJ  (OFF_QKV  + 12*QKV_T)
#define OFF_FC1   (OFF_PROJ + 12*PROJ_T)
#define OFF_FC2   (OFF_FC1  + 12*FC1_T)
#define OFF_PATCH (OFF_FC2  + 12*FC2_T)
#define WTOT      (OFF_PATCH + 768*768)
#define MSZ (HEADS*NTOK*NTOK)
#define NN (NTOK*NTOK)

// ---------------- device scratch ----------------
__device__ __half g_wh[WTOT];
__device__ __half g_hh[ROWS*CDIM],  g_hl[ROWS*CDIM];
__device__ __half g_oh[ROWS*CDIM],  g_ol[ROWS*CDIM];
__device__ __half g_h2h[ROWS*HID],  g_h2l[ROWS*HID];
__device__ __half g_pah[PROWS*CDIM],g_pal[PROWS*CDIM];
__device__ float g_x[ROWS*CDIM];
__device__ float g_qkv[ROWS*3*CDIM];
__device__ float g_M[DEPTH*MSZ];
__device__ float g_pt[PROWS*CDIM];
__device__ float g_cls[BATCH*CDIM];

// ---------------- helpers ----------------
__device__ __forceinline__ float warpMax(float v){
#pragma unroll
  for (int o=16;o;o>>=1) v = fmaxf(v, __shfl_xor_sync(0xffffffffu, v, o));
  return v;
}
__device__ __forceinline__ float warpSum(float v){
#pragma unroll
  for (int o=16;o;o>>=1) v += __shfl_xor_sync(0xffffffffu, v, o);
  return v;
}
__device__ __forceinline__ uint32_t cvta_s(const void* p){
  return (uint32_t)__cvta_generic_to_shared(p);
}
__device__ __forceinline__ void mma16816(float* c, const uint32_t* a, const uint32_t* b){
  asm volatile(
    "mma.sync.aligned.m16n8k16.row.col.f32.f16.f16.f32 "
    "{%0,%1,%2,%3},{%4,%5,%6,%7},{%8,%9},{%0,%1,%2,%3};"
    : "+f"(c[0]), "+f"(c[1]), "+f"(c[2]), "+f"(c[3])
    : "r"(a[0]), "r"(a[1]), "r"(a[2]), "r"(a[3]), "r"(b[0]), "r"(b[1]));
}
__device__ __forceinline__ void ldm_x4(uint32_t* r, uint32_t addr){
  asm volatile("ldmatrix.sync.aligned.m8n8.x4.shared.b16 {%0,%1,%2,%3},[%4];"
    : "=r"(r[0]), "=r"(r[1]), "=r"(r[2]), "=r"(r[3]) : "r"(addr));
}
__device__ __forceinline__ void cp_async16(uint32_t dst, const void* src, int szbytes){
  asm volatile("cp.async.cg.shared.global [%0], [%1], 16, %2;"
               :: "r"(dst), "l"(src), "r"(szbytes) : "memory");
}
#define CP_COMMIT() asm volatile("cp.async.commit_group;" ::: "memory")
#define CP_WAIT(n)  asm volatile("cp.async.wait_group %0;" :: "n"(n) : "memory")

__device__ __forceinline__ uint32_t swz(int row, int ch){
  return (uint32_t)row*64u + (uint32_t)((ch ^ ((row>>1)&3)) << 4);
}
__device__ __forceinline__ void split2h(float v, __half* hh, __half* hl){
  __half h = __float2half_rn(v);
  *hh = h;
  *hl = __float2half_rn(v - __half2float(h));
}

// ---------------- weight preprocessing (batched over layers) ----------------
__global__ void tsplit_kernel(const float* __restrict__ W0, __half* __restrict__ Th0,
                              int K, int N){
  __shared__ float t[32][33];
  const float* W = W0 + (size_t)blockIdx.z * K * N;
  __half* Th = Th0 + (size_t)blockIdx.z * K * N;
  int k0 = blockIdx.y*32, n0 = blockIdx.x*32;
  int tx = threadIdx.x, ty = threadIdx.y;
#pragma unroll
  for (int i=0;i<32;i+=8){
    int k = k0+ty+i, n = n0+tx;
    t[ty+i][tx] = (k<K && n<N) ? W[(size_t)k*N+n] : 0.0f;
  }
  __syncthreads();
#pragma unroll
  for (int i=0;i<32;i+=8){
    int n = n0+ty+i, k = k0+tx;
    if (n<N && k<K) Th[(size_t)n*K+k] = __float2half_rn(t[tx][ty+i]);
  }
}

__global__ void split_pw_kernel(const float* __restrict__ W, __half* __restrict__ Th){
  int idx = blockIdx.x*256 + threadIdx.x;
  if (idx >= CDIM*CDIM) return;
  Th[idx] = __float2half_rn(W[idx]);
}

// ---------------- patch embed ----------------
__global__ void im2col_kernel(const float* __restrict__ img,
                              __half* __restrict__ ph, __half* __restrict__ pl){
  int idx = blockIdx.x*256 + threadIdx.x;
  if (idx >= PROWS*CDIM) return;
  int row = idx / CDIM, k = idx % CDIM;
  int b = row / NPATCH, p = row % NPATCH;
  int py = p / SGRID, px = p % SGRID;
  int ci = k / (PSZ*PSZ), rr = k % (PSZ*PSZ);
  int phh = rr / PSZ, pww = rr % PSZ;
  float v = img[ ((size_t)(b*3 + ci)*IMG + (py*PSZ + phh))*IMG + (px*PSZ + pww) ];
  split2h(v, &ph[idx], &pl[idx]);
}

__global__ void assemble_ln_kernel(const float* __restrict__ pt, const float* __restrict__ cls_tok,
                                   const float* __restrict__ pos, const float* __restrict__ pbias,
                                   const float* __restrict__ w, const float* __restrict__ b,
                                   float* __restrict__ x,
                                   __half* __restrict__ oh, __half* __restrict__ ol){
  __shared__ float redS[8], redQ[8];
  __shared__ float s_mean, s_inv;
  int r = blockIdx.x;
  int bb = r / NTOK, n = r % NTOK;
  int tid = threadIdx.x, lane = tid & 31, wid = tid >> 5;

  float vv[3];
#pragma unroll
  for (int e = 0; e < 3; ++e){
    int c = tid + e*256;
    float v;
    if (n == 0) v = cls_tok[c];
    else        v = pt[(size_t)(bb*NPATCH + (n-1))*CDIM + c] + pbias[c];
    v += pos[n*CDIM + c];
    vv[e] = v;
    x[(size_t)r*CDIM + c] = v;
  }
  float s = vv[0]+vv[1]+vv[2];
  float q = vv[0]*vv[0]+vv[1]*vv[1]+vv[2]*vv[2];
  s = warpSum(s); q = warpSum(q);
  if (lane == 0){ redS[wid] = s; redQ[wid] = q; }
  __syncthreads();
  if (tid == 0){
    float ts = 0.0f, tq = 0.0f;
#pragma unroll
    for (int i = 0; i < 8; ++i){ ts += redS[i]; tq += redQ[i]; }
    float mean = ts * (1.0f/CDIM);
    s_mean = mean;
    s_inv = rsqrtf(tq * (1.0f/CDIM) - mean*mean + 1e-5f);
  }
  __syncthreads();
  float mean = s_mean, inv = s_inv;
#pragma unroll
  for (int e = 0; e < 3; ++e){
    int c = tid + e*256;
    float y = (vv[e] - mean) * inv * w[c] + b[c];
    split2h(y, &oh[(size_t)r*CDIM + c], &ol[(size_t)r*CDIM + c]);
  }
}

// ---------------- M via lookup tables, D fused inline ----------------
__global__ void compute_M_kernel(const float* __restrict__ ai, const int* __restrict__ ci,
                                 float* __restrict__ M12){
  __shared__ float table[HEADS][NCURVES][196];
  __shared__ int cis[NCURVES*NPATCH];
  int tid = threadIdx.x;
  int layer = blockIdx.z;
  for (int e = tid; e < NCURVES*NPATCH; e += 256) cis[e] = ci[e];
  for (int e = tid; e < HEADS*NCURVES*196; e += 256){
    int h = e / (NCURVES*196);
    int rem = e % (NCURVES*196);
    int c = rem / 196, dd = rem % 196;
    float a = ai[layer*NCURVES*HEADS + c*HEADS + h];
    float sig = 1.0f/(1.0f + expf(-a));
    table[h][c][dd] = exp2f((float)dd * log2f(sig));
  }
  __syncthreads();

  int idx = blockIdx.x*256 + tid;
  if (idx >= NN) return;
  int i = idx / NTOK, j = idx % NTOK;
  float* Mout = M12 + (size_t)layer*MSZ + idx;
  if (i == 0 || j == 0){
#pragma unroll
    for (int h = 0; h < HEADS; ++h)
      Mout[(size_t)h*NN] = 1.0f;
  } else {
    int dv[NCURVES];
#pragma unroll
    for (int c = 0; c < NCURVES; ++c){
      int d = cis[c*NPATCH + (i-1)] - cis[c*NPATCH + (j-1)];
      dv[c] = d < 0 ? -d : d;
    }
#pragma unroll
    for (int h = 0; h < HEADS; ++h){
      float acc = 0.0f;
#pragma unroll
      for (int c = 0; c < NCURVES; ++c)
        acc += table[h][c][dv[c]];
      Mout[(size_t)h*NN] = acc * (1.0f/6.0f);
    }
  }
}

// ---------------- layernorm ----------------
template<int PAIR>
__global__ void layernorm_kernel(const float* __restrict__ in, long in_stride,
                                 const float* __restrict__ w, const float* __restrict__ b,
                                 float* __restrict__ outf,
                                 __half* __restrict__ oh, __half* __restrict__ ol){
  __shared__ float redS[8], redQ[8];
  __shared__ float s_mean, s_inv;
  int r = blockIdx.x;
  const float* xr = in + (long)r * in_stride;
  int tid = threadIdx.x, lane = tid & 31, wid = tid >> 5;

  float v0 = xr[tid], v1 = xr[tid+256], v2 = xr[tid+512];
  float s = v0 + v1 + v2;
  float q = v0*v0 + v1*v1 + v2*v2;
  s = warpSum(s); q = warpSum(q);
  if (lane == 0){ redS[wid] = s; redQ[wid] = q; }
  __syncthreads();
  if (tid == 0){
    float ts = 0.0f, tq = 0.0f;
#pragma unroll
    for (int i = 0; i < 8; ++i){ ts += redS[i]; tq += redQ[i]; }
    float mean = ts * (1.0f/CDIM);
    s_mean = mean;
    s_inv = rsqrtf(tq * (1.0f/CDIM) - mean*mean + 1e-5f);
  }
  __syncthreads();
  float mean = s_mean, inv = s_inv;
#pragma unroll
  for (int e = 0; e < 3; ++e){
    int c = tid + e*256;
    float xv = (e==0) ? v0 : (e==1) ? v1 : v2;
    float y = (xv - mean) * inv * w[c] + b[c];
    if (PAIR){
      split2h(y, &oh[(size_t)r*CDIM + c], &ol[(size_t)r*CDIM + c]);
    } else {
      outf[(size_t)r*CDIM + c] = y;
    }
  }
}

// ---------------- split-fp16 MMA GEMM: 128x128, 3-stage, fragment-pipelined ----------------
// EPI 0: fp32 store. 2: +bias +res -> fp32 store. 3: +bias, GELU -> fp16 pair.
// EPI 4: split-K partial -> atomicAdd into Cf (res pre-resident); bias by z==0.
template<int EPI>
__global__ void __launch_bounds__(256, 2)
mma_gemm_kernel(const __half* __restrict__ Ah_, const __half* __restrict__ Al_,
                const __half* __restrict__ Bh_,
                const float* __restrict__ bias, const float* __restrict__ res,
                float* __restrict__ Cf, __half* __restrict__ Ch, __half* __restrict__ Cl,
                int M, int N, int K, int Kchunk){
  extern __shared__ __align__(16) char dsm[];
  uint32_t sb = cvta_s(dsm);  // [3 stages][AH 8K | AL 8K | BH 8K]

  int tid = threadIdx.x, wid = tid >> 5, lane = tid & 31;
  int m0 = blockIdx.y * 128, n0 = blockIdx.x * 128;
  int kbase = blockIdx.z * Kchunk;
  int warp_m = wid >> 2, warp_n = wid & 3;
  int lam = lane & 15, lau = lane >> 4;

  float acc[4][4][4];
#pragma unroll
  for (int a=0;a<4;++a)
#pragma unroll
    for (int b=0;b<4;++b)
#pragma unroll
      for (int c=0;c<4;++c) acc[a][b][c] = 0.0f;

  auto load_stage = [&](int it, int s){
    int k0 = kbase + it * 32;
    uint32_t st = sb + (uint32_t)s*24576u;
#pragma unroll
    for (int i = 0; i < 2; ++i){
      int c = i*256 + tid;
      int row = c >> 2, ch = c & 3;
      int gr = m0 + row;
      int ok = gr < M;
      cp_async16(st + swz(row,ch), Ah_ + (size_t)(ok?gr:0)*K + k0 + ch*8, ok?16:0);
    }
#pragma unroll
    for (int i = 0; i < 2; ++i){
      int c = i*256 + tid;
      int row = c >> 2, ch = c & 3;
      int gr = m0 + row;
      int ok = gr < M;
      cp_async16(st + 8192u + swz(row,ch), Al_ + (size_t)(ok?gr:0)*K + k0 + ch*8, ok?16:0);
    }
#pragma unroll
    for (int i = 0; i < 2; ++i){
      int c = i*256 + tid;
      int row = c >> 2, ch = c & 3;
      cp_async16(st + 16384u + swz(row,ch), Bh_ + (size_t)(n0+row)*K + k0 + ch*8, 16);
    }
  };

  int niter = Kchunk >> 5;
  load_stage(0, 0); CP_COMMIT();
  load_stage(1, 1); CP_COMMIT();

  // B fragment row/chunk components (compile-time per k16 below)
  int brow0 = warp_n*32 +      (lane & 7) + ((lane >> 4) << 3);
  int brow1 = warp_n*32 + 16 + (lane & 7) + ((lane >> 4) << 3);
  int bchp  = (lane >> 3) & 1;
  int arow0 = warp_m*64 + lam;

  for (int it = 0; it < niter; ++it){
    CP_WAIT(1);
    __syncthreads();
    if (it + 2 < niter) load_stage(it + 2, (it + 2) % 3);
    CP_COMMIT();

    int s = it % 3;
    uint32_t Abh = sb + (uint32_t)s*24576u;
    uint32_t Abl = Abh + 8192u;
    uint32_t Bbh = Abh + 16384u;

    // --- fragment-pipelined mainloop ---
    uint32_t bf[2][2][4];    // [k16][g]
    uint32_t ah[2][4], al[2][4];
    // preload: B(k16=0) and A(mt=0,k16=0)
    ldm_x4(bf[0][0], Bbh + swz(brow0, 0*2 + bchp));
    ldm_x4(bf[0][1], Bbh + swz(brow1, 0*2 + bchp));
    {
      uint32_t aoff = swz(arow0, 0*2 + lau);
      ldm_x4(ah[0], Abh + aoff);
      ldm_x4(al[0], Abl + aoff);
    }
#pragma unroll
    for (int k16 = 0; k16 < 2; ++k16){
#pragma unroll
      for (int mt = 0; mt < 4; ++mt){
        int cur = (k16*4 + mt) & 1;
        int nxt = cur ^ 1;
        // prefetch next A fragment (next mt, or mt=0 of next k16)
        if (mt < 3){
          uint32_t aoff = swz(arow0 + (mt+1)*16, k16*2 + lau);
          ldm_x4(ah[nxt], Abh + aoff);
          ldm_x4(al[nxt], Abl + aoff);
        } else if (k16 == 0){
          uint32_t aoff = swz(arow0, 1*2 + lau);
          ldm_x4(ah[nxt], Abh + aoff);
          ldm_x4(al[nxt], Abl + aoff);
        }
        // prefetch B for k16=1 early (during k16=0, mt=0)
        if (k16 == 0 && mt == 0){
          ldm_x4(bf[1][0], Bbh + swz(brow0, 1*2 + bchp));
          ldm_x4(bf[1][1], Bbh + swz(brow1, 1*2 + bchp));
        }
        mma16816(acc[mt][0], ah[cur], bf[k16][0]+0);
        mma16816(acc[mt][1], ah[cur], bf[k16][0]+2);
        mma16816(acc[mt][2], ah[cur], bf[k16][1]+0);
        mma16816(acc[mt][3], ah[cur], bf[k16][1]+2);
        mma16816(acc[mt][0], al[cur], bf[k16][0]+0);
        mma16816(acc[mt][1], al[cur], bf[k16][0]+2);
        mma16816(acc[mt][2], al[cur], bf[k16][1]+0);
        mma16816(acc[mt][3], al[cur], bf[k16][1]+2);
      }
    }
  }

  // epilogue
#pragma unroll
  for (int mt = 0; mt < 4; ++mt){
#pragma unroll
    for (int nt = 0; nt < 4; ++nt){
#pragma unroll
      for (int half = 0; half < 2; ++half){
        int gm = m0 + warp_m*64 + mt*16 + (lane >> 2) + half*8;
        if (gm >= M) continue;
#pragma unroll
        for (int e = 0; e < 2; ++e){
          int gn = n0 + warp_n*32 + nt*8 + 2*(lane & 3) + e;
          float v = acc[mt][nt][half*2 + e];
          if (EPI == 0){
            Cf[(size_t)gm*N + gn] = v;
          } else if (EPI == 2){
            v += bias[gn] + res[(size_t)gm*N + gn];
            Cf[(size_t)gm*N + gn] = v;
          } else if (EPI == 4){
            if (blockIdx.z == 0) v += bias[gn];
            atomicAdd(&Cf[(size_t)gm*N + gn], v);
          } else {
            v += bias[gn];
            float g = 0.5f * v * (1.0f + erff(v * 0.7071067811865475f));
            split2h(g, &Ch[(size_t)gm*N + gn], &Cl[(size_t)gm*N + gn]);
          }
        }
      }
    }
  }
}

// ---------------- attention: warp-per-row, 8 warps, ILP'd PV loop ----------------
__global__ void __launch_bounds__(256)
attention_kernel(const float* __restrict__ qkv, const float* __restrict__ M,
                 __half* __restrict__ oh, __half* __restrict__ ol){
  extern __shared__ float sm[];
  float* ks = sm;
  float* vs = ks + NTOK*KSTRIDE;
  float* qs = vs + NTOK*KSTRIDE;
  float* ps = qs + 8*68;

  int bh = blockIdx.x;
  int b = bh / HEADS, h = bh % HEADS;
  int tid = threadIdx.x, lane = tid & 31, wid = tid >> 5;
  const float scale = 0.125f;

  size_t base = (size_t)b * NTOK * 3 * CDIM;
  for (int idx = tid; idx < NTOK*16; idx += 256){
    int j = idx >> 4, d4 = idx & 15;
    float4 kv = *(const float4*)(qkv + base + (size_t)j*3*CDIM + CDIM   + h*HDIM + d4*4);
    float4 vv = *(const float4*)(qkv + base + (size_t)j*3*CDIM + 2*CDIM + h*HDIM + d4*4);
    *(float4*)(ks + j*KSTRIDE + d4*4) = kv;
    *(float4*)(vs + j*KSTRIDE + d4*4) = vv;
  }
  __syncthreads();

  const float* Mh = M + (size_t)h * NN;
  float* qw = qs + wid*68;
  float* pw = ps + wid*224;

  for (int i = wid; i < NTOK; i += 8){
    if (lane < 16)
      *(float4*)(qw + lane*4) = *(const float4*)(qkv + base + (size_t)i*3*CDIM + h*HDIM + lane*4);
    __syncwarp();

    float sj[7];
    float mx = -1e30f;
#pragma unroll
    for (int jj = 0; jj < 7; ++jj){
      int j = lane + jj*32;
      float acc = -1e30f;
      if (j < NTOK){
        const float4* k4 = (const float4*)(ks + j*KSTRIDE);
        const float4* q4 = (const float4*)qw;
        float a = 0.0f;
#pragma unroll
        for (int d4 = 0; d4 < 16; ++d4){
          float4 kv = k4[d4], qv = q4[d4];
          a += qv.x*kv.x + qv.y*kv.y + qv.z*kv.z + qv.w*kv.w;
        }
        acc = a * scale * Mh[(size_t)i*NTOK + j];
      }
      sj[jj] = acc;
      mx = fmaxf(mx, acc);
    }
    mx = warpMax(mx);
    float sum = 0.0f;
#pragma unroll
    for (int jj = 0; jj < 7; ++jj){
      int j = lane + jj*32;
      float p = (j < NTOK) ? __expf(sj[jj] - mx) : 0.0f;
      pw[j] = p;
      sum += p;
    }
    sum = warpSum(sum);
    float rinv = 1.0f / sum;
    __syncwarp();

    float a0 = 0.f, a1 = 0.f, b0 = 0.f, b1 = 0.f;
    float c0 = 0.f, c1 = 0.f, d0 = 0.f, d1 = 0.f;
    int j = 0;
    for (; j + 4 <= 196; j += 4){
      float p0 = pw[j], p1 = pw[j+1], p2 = pw[j+2], p3 = pw[j+3];
      float2 v0 = *(const float2*)(vs + (j  )*KSTRIDE + lane*2);
      float2 v1 = *(const float2*)(vs + (j+1)*KSTRIDE + lane*2);
      float2 v2 = *(const float2*)(vs + (j+2)*KSTRIDE + lane*2);
      float2 v3 = *(const float2*)(vs + (j+3)*KSTRIDE + lane*2);
      a0 += p0*v0.x; a1 += p0*v0.y;
      b0 += p1*v1.x; b1 += p1*v1.y;
      c0 += p2*v2.x; c1 += p2*v2.y;
      d0 += p3*v3.x; d1 += p3*v3.y;
    }
    {
      float p = pw[196];
      float2 vv = *(const float2*)(vs + 196*KSTRIDE + lane*2);
      a0 += p*vv.x; a1 += p*vv.y;
    }
    float o0 = ((a0 + b0) + (c0 + d0)) * rinv;
    float o1 = ((a1 + b1) + (c1 + d1)) * rinv;
    size_t oidx = ((size_t)(b*NTOK + i))*CDIM + h*HDIM + lane*2;
    split2h(o0, &oh[oidx],   &ol[oidx]);
    split2h(o1, &oh[oidx+1], &ol[oidx+1]);
    __syncwarp();
  }
}

// ---------------- classifier head ----------------
__global__ void head_kernel(const float* __restrict__ cls, const float* __restrict__ W,
                            const float* __restrict__ bias, float* __restrict__ out){
  __shared__ float cs[CDIM];
  int b = blockIdx.y;
  int n = blockIdx.x*256 + threadIdx.x;
  for (int k = threadIdx.x; k < CDIM; k += 256) cs[k] = cls[b*CDIM + k];
  __syncthreads();
  if (n < NCLS){
    float acc = bias[n];
#pragma unroll 4
    for (int k = 0; k < CDIM; ++k)
      acc += cs[k] * W[(size_t)k*NCLS + n];
    out[b*NCLS + n] = acc;
  }
}

// ---------------- launcher ----------------
extern "C" void kernel_launch(void* const* d_in, const int* in_sizes, int n_in,
                              void* d_out, int out_size){
  (void)in_sizes; (void)n_in; (void)out_size;
  const float* images  = (const float*)d_in[0];
  const float* patch_w = (const float*)d_in[1];
  const float* patch_b = (const float*)d_in[2];
  const float* cls_tok = (const float*)d_in[3];
  const float* pos_emb = (const float*)d_in[4];
  const float* ln1_w   = (const float*)d_in[5];
  const float* ln1_b   = (const float*)d_in[6];
  const float* qkv_w   = (const float*)d_in[7];
  const float* proj_w  = (const float*)d_in[8];
  const float* proj_b  = (const float*)d_in[9];
  const float* ai      = (const float*)d_in[10];
  const float* ln2_w   = (const float*)d_in[11];
  const float* ln2_b   = (const float*)d_in[12];
  const float* fc1_w   = (const float*)d_in[13];
  const float* fc1_b   = (const float*)d_in[14];
  const float* fc2_w   = (const float*)d_in[15];
  const float* fc2_b   = (const float*)d_in[16];
  const float* norm_w  = (const float*)d_in[17];
  const float* norm_b  = (const float*)d_in[18];
  const float* head_w  = (const float*)d_in[19];
  const float* head_b  = (const float*)d_in[20];
  const int*   curve   = (const int*)d_in[21];
  float* out = (float*)d_out;

  __half *wh,*hh,*hl,*oh,*ol,*h2h,*h2l,*pah,*pal;
  float *x,*qkvb,*Mb,*pt,*cls;
  cudaGetSymbolAddress((void**)&wh,  g_wh);
  cudaGetSymbolAddress((void**)&hh,  g_hh);
  cudaGetSymbolAddress((void**)&hl,  g_hl);
  cudaGetSymbolAddress((void**)&oh,  g_oh);
  cudaGetSymbolAddress((void**)&ol,  g_ol);
  cudaGetSymbolAddress((void**)&h2h, g_h2h);
  cudaGetSymbolAddress((void**)&h2l, g_h2l);
  cudaGetSymbolAddress((void**)&pah, g_pah);
  cudaGetSymbolAddress((void**)&pal, g_pal);
  cudaGetSymbolAddress((void**)&x,   g_x);
  cudaGetSymbolAddress((void**)&qkvb,g_qkv);
  cudaGetSymbolAddress((void**)&Mb,  g_M);
  cudaGetSymbolAddress((void**)&pt,  g_pt);
  cudaGetSymbolAddress((void**)&cls, g_cls);

  const int attSmem = (2*NTOK*KSTRIDE + 8*68 + 8*224) * (int)sizeof(float);
  cudaFuncSetAttribute(attention_kernel, cudaFuncAttributeMaxDynamicSharedMemorySize, attSmem);
  const int gemmSmem = 73728;  // 3 stages x 24KB
  cudaFuncSetAttribute(mma_gemm_kernel<0>, cudaFuncAttributeMaxDynamicSharedMemorySize, gemmSmem);
  cudaFuncSetAttribute(mma_gemm_kernel<2>, cudaFuncAttributeMaxDynamicSharedMemorySize, gemmSmem);
  cudaFuncSetAttribute(mma_gemm_kernel<3>, cudaFuncAttributeMaxDynamicSharedMemorySize, gemmSmem);
  cudaFuncSetAttribute(mma_gemm_kernel<4>, cudaFuncAttributeMaxDynamicSharedMemorySize, gemmSmem);

  dim3 tb(32, 8);
  const int mt = (ROWS + 127)/128;   // 50
  const int pmt = (PROWS + 127)/128; // 49

  // ---- ordered so launch #6 (ncu -s 5 -c 1) is the layer-0 QKV GEMM ----
  im2col_kernel<<<(PROWS*CDIM+255)/256, 256>>>(images, pah, pal);                         // 1
  split_pw_kernel<<<(CDIM*CDIM+255)/256, 256>>>(patch_w, wh + OFF_PATCH);                 // 2
  tsplit_kernel<<<dim3(2304/32, 768/32, DEPTH), tb>>>(qkv_w,  wh + OFF_QKV,  768, 2304);  // 3
  mma_gemm_kernel<0><<<dim3(768/128, pmt), 256, gemmSmem>>>(                              // 4
      pah, pal, wh + OFF_PATCH,
      nullptr, nullptr, pt, nullptr, nullptr, PROWS, 768, 768, 768);
  assemble_ln_kernel<<<ROWS, 256>>>(pt, cls_tok, pos_emb, patch_b, ln1_w, ln1_b, x, hh, hl); // 5
  mma_gemm_kernel<0><<<dim3(2304/128, mt), 256, gemmSmem>>>(                              // 6 <- profiled
      hh, hl, wh + OFF_QKV,
      nullptr, nullptr, qkvb, nullptr, nullptr, ROWS, 2304, 768, 768);
  tsplit_kernel<<<dim3(768/32,  768/32, DEPTH), tb>>>(proj_w, wh + OFF_PROJ, 768, 768);   // 7
  tsplit_kernel<<<dim3(3072/32, 768/32, DEPTH), tb>>>(fc1_w,  wh + OFF_FC1,  768, 3072);  // 8
  tsplit_kernel<<<dim3(768/32, 3072/32, DEPTH), tb>>>(fc2_w,  wh + OFF_FC2,  3072, 768);  // 9
  compute_M_kernel<<<dim3((NN+255)/256, 1, DEPTH), 256>>>(ai, curve, Mb);                 // 10

  for (int d = 0; d < DEPTH; ++d){
    if (d > 0){
      layernorm_kernel<1><<<ROWS, 256>>>(x, CDIM, ln1_w + d*CDIM, ln1_b + d*CDIM, nullptr, hh, hl);
      mma_gemm_kernel<0><<<dim3(2304/128, mt), 256, gemmSmem>>>(
          hh, hl, wh + OFF_QKV + (size_t)d*QKV_T,
          nullptr, nullptr, qkvb, nullptr, nullptr, ROWS, 2304, 768, 768);
    }
    attention_kernel<<<BATCH*HEADS, 256, attSmem>>>(qkvb, Mb + (size_t)d*MSZ, oh, ol);
    mma_gemm_kernel<4><<<dim3(768/128, mt, 2), 256, gemmSmem>>>(
        oh, ol, wh + OFF_PROJ + (size_t)d*PROJ_T,
        proj_b + d*CDIM, nullptr, x, nullptr, nullptr, ROWS, 768, 768, 384);
    layernorm_kernel<1><<<ROWS, 256>>>(x, CDIM, ln2_w + d*CDIM, ln2_b + d*CDIM, nullptr, hh, hl);
    mma_gemm_kernel<3><<<dim3(3072/128, mt), 256, gemmSmem>>>(
        hh, hl, wh + OFF_FC1 + (size_t)d*FC1_T,
        fc1_b + d*HID, nullptr, nullptr, h2h, h2l, ROWS, 3072, 768, 768);
    mma_gemm_kernel<4><<<dim3(768/128, mt, 4), 256, gemmSmem>>>(
        h2h, h2l, wh + OFF_FC2 + (size_t)d*FC2_T,
        fc2_b + d*CDIM, nullptr, x, nullptr, nullptr, ROWS, 768, 3072, 768);
  }

  layernorm_kernel<0><<<BATCH, 256>>>(x, (long)NTOK*CDIM, norm_w, norm_b, cls, nullptr, nullptr);
  head_kernel<<<dim3(4, BATCH), 256>>>(cls, head_w, head_b, out);
}

// round 16
// speedup vs baseline: 1.0104x; 1.0085x over previous
#include <cuda_runtime.h>
#include <cuda_fp16.h>
#include <math.h>
#include <stdint.h>

#define BATCH 32
#define IMG 224
#define PSZ 16
#define SGRID 14
#define NPATCH 196
#define NTOK 197
#define CDIM 768
#define HEADS 12
#define HDIM 64
#define DEPTH 12
#define HID 3072
#define NCLS 1000
#define NCURVES 6
#define ROWS (BATCH*NTOK)     /* 6304 */
#define PROWS (BATCH*NPATCH)  /* 6272 */
#define KSTRIDE 68

#define QKV_T   (2304*768)
#define PROJ_T  (768*768)
#define FC1_T   (768*3072)
#define FC2_T   (3072*768)
#define OFF_QKV   0
#define OFF_PROJ  (OFF_QKV  + 12*QKV_T)
#define OFF_FC1   (OFF_PROJ + 12*PROJ_T)
#define OFF_FC2   (OFF_FC1  + 12*FC1_T)
#define OFF_PATCH (OFF_FC2  + 12*FC2_T)
#define WTOT      (OFF_PATCH + 768*768)
#define MSZ (HEADS*NTOK*NTOK)
#define NN (NTOK*NTOK)

// ---------------- device scratch ----------------
__device__ __half g_wh[WTOT];
__device__ __half g_hh[ROWS*CDIM],  g_hl[ROWS*CDIM];
__device__ __half g_oh[ROWS*CDIM],  g_ol[ROWS*CDIM];
__device__ __half g_h2h[ROWS*HID],  g_h2l[ROWS*HID];
__device__ __half g_pah[PROWS*CDIM],g_pal[PROWS*CDIM];
__device__ float g_x[ROWS*CDIM];
__device__ float g_qkv[ROWS*3*CDIM];
__device__ float g_M[DEPTH*MSZ];
__device__ float g_pt[PROWS*CDIM];
__device__ float g_cls[BATCH*CDIM];

// ---------------- helpers ----------------
__device__ __forceinline__ float warpMax(float v){
#pragma unroll
  for (int o=16;o;o>>=1) v = fmaxf(v, __shfl_xor_sync(0xffffffffu, v, o));
  return v;
}
__device__ __forceinline__ float warpSum(float v){
#pragma unroll
  for (int o=16;o;o>>=1) v += __shfl_xor_sync(0xffffffffu, v, o);
  return v;
}
__device__ __forceinline__ uint32_t cvta_s(const void* p){
  return (uint32_t)__cvta_generic_to_shared(p);
}
__device__ __forceinline__ void mma16816(float* c, const uint32_t* a, const uint32_t* b){
  asm volatile(
    "mma.sync.aligned.m16n8k16.row.col.f32.f16.f16.f32 "
    "{%0,%1,%2,%3},{%4,%5,%6,%7},{%8,%9},{%0,%1,%2,%3};"
    : "+f"(c[0]), "+f"(c[1]), "+f"(c[2]), "+f"(c[3])
    : "r"(a[0]), "r"(a[1]), "r"(a[2]), "r"(a[3]), "r"(b[0]), "r"(b[1]));
}
__device__ __forceinline__ void ldm_x4(uint32_t* r, uint32_t addr){
  asm volatile("ldmatrix.sync.aligned.m8n8.x4.shared.b16 {%0,%1,%2,%3},[%4];"
    : "=r"(r[0]), "=r"(r[1]), "=r"(r[2]), "=r"(r[3]) : "r"(addr));
}
__device__ __forceinline__ void cp_async16(uint32_t dst, const void* src, int szbytes){
  asm volatile("cp.async.cg.shared.global [%0], [%1], 16, %2;"
               :: "r"(dst), "l"(src), "r"(szbytes) : "memory");
}
#define CP_COMMIT() asm volatile("cp.async.commit_group;" ::: "memory")
#define CP_WAIT(n)  asm volatile("cp.async.wait_group %0;" :: "n"(n) : "memory")

__device__ __forceinline__ uint32_t swz(int row, int ch){
  return (uint32_t)row*64u + (uint32_t)((ch ^ ((row>>1)&3)) << 4);
}
__device__ __forceinline__ void split2h(float v, __half* hh, __half* hl){
  __half h = __float2half_rn(v);
  *hh = h;
  *hl = __float2half_rn(v - __half2float(h));
}

// ---------------- weight preprocessing (batched over layers) ----------------
__global__ void tsplit_kernel(const float* __restrict__ W0, __half* __restrict__ Th0,
                              int K, int N){
  __shared__ float t[32][33];
  const float* W = W0 + (size_t)blockIdx.z * K * N;
  __half* Th = Th0 + (size_t)blockIdx.z * K * N;
  int k0 = blockIdx.y*32, n0 = blockIdx.x*32;
  int tx = threadIdx.x, ty = threadIdx.y;
#pragma unroll
  for (int i=0;i<32;i+=8){
    int k = k0+ty+i, n = n0+tx;
    t[ty+i][tx] = (k<K && n<N) ? W[(size_t)k*N+n] : 0.0f;
  }
  __syncthreads();
#pragma unroll
  for (int i=0;i<32;i+=8){
    int n = n0+ty+i, k = k0+tx;
    if (n<N && k<K) Th[(size_t)n*K+k] = __float2half_rn(t[tx][ty+i]);
  }
}

__global__ void split_pw_kernel(const float* __restrict__ W, __half* __restrict__ Th){
  int idx = blockIdx.x*256 + threadIdx.x;
  if (idx >= CDIM*CDIM) return;
  Th[idx] = __float2half_rn(W[idx]);
}

// ---------------- patch embed ----------------
__global__ void im2col_kernel(const float* __restrict__ img,
                              __half* __restrict__ ph, __half* __restrict__ pl){
  int idx = blockIdx.x*256 + threadIdx.x;
  if (idx >= PROWS*CDIM) return;
  int row = idx / CDIM, k = idx % CDIM;
  int b = row / NPATCH, p = row % NPATCH;
  int py = p / SGRID, px = p % SGRID;
  int ci = k / (PSZ*PSZ), rr = k % (PSZ*PSZ);
  int phh = rr / PSZ, pww = rr % PSZ;
  float v = img[ ((size_t)(b*3 + ci)*IMG + (py*PSZ + phh))*IMG + (px*PSZ + pww) ];
  split2h(v, &ph[idx], &pl[idx]);
}

__global__ void assemble_ln_kernel(const float* __restrict__ pt, const float* __restrict__ cls_tok,
                                   const float* __restrict__ pos, const float* __restrict__ pbias,
                                   const float* __restrict__ w, const float* __restrict__ b,
                                   float* __restrict__ x,
                                   __half* __restrict__ oh, __half* __restrict__ ol){
  __shared__ float redS[8], redQ[8];
  __shared__ float s_mean, s_inv;
  int r = blockIdx.x;
  int bb = r / NTOK, n = r % NTOK;
  int tid = threadIdx.x, lane = tid & 31, wid = tid >> 5;

  float vv[3];
#pragma unroll
  for (int e = 0; e < 3; ++e){
    int c = tid + e*256;
    float v;
    if (n == 0) v = cls_tok[c];
    else        v = pt[(size_t)(bb*NPATCH + (n-1))*CDIM + c] + pbias[c];
    v += pos[n*CDIM + c];
    vv[e] = v;
    x[(size_t)r*CDIM + c] = v;
  }
  float s = vv[0]+vv[1]+vv[2];
  float q = vv[0]*vv[0]+vv[1]*vv[1]+vv[2]*vv[2];
  s = warpSum(s); q = warpSum(q);
  if (lane == 0){ redS[wid] = s; redQ[wid] = q; }
  __syncthreads();
  if (tid == 0){
    float ts = 0.0f, tq = 0.0f;
#pragma unroll
    for (int i = 0; i < 8; ++i){ ts += redS[i]; tq += redQ[i]; }
    float mean = ts * (1.0f/CDIM);
    s_mean = mean;
    s_inv = rsqrtf(tq * (1.0f/CDIM) - mean*mean + 1e-5f);
  }
  __syncthreads();
  float mean = s_mean, inv = s_inv;
#pragma unroll
  for (int e = 0; e < 3; ++e){
    int c = tid + e*256;
    float y = (vv[e] - mean) * inv * w[c] + b[c];
    split2h(y, &oh[(size_t)r*CDIM + c], &ol[(size_t)r*CDIM + c]);
  }
}

// ---------------- M via lookup tables, D fused inline ----------------
__global__ void compute_M_kernel(const float* __restrict__ ai, const int* __restrict__ ci,
                                 float* __restrict__ M12){
  __shared__ float table[HEADS][NCURVES][196];
  __shared__ int cis[NCURVES*NPATCH];
  int tid = threadIdx.x;
  int layer = blockIdx.z;
  for (int e = tid; e < NCURVES*NPATCH; e += 256) cis[e] = ci[e];
  for (int e = tid; e < HEADS*NCURVES*196; e += 256){
    int h = e / (NCURVES*196);
    int rem = e % (NCURVES*196);
    int c = rem / 196, dd = rem % 196;
    float a = ai[layer*NCURVES*HEADS + c*HEADS + h];
    float sig = 1.0f/(1.0f + expf(-a));
    table[h][c][dd] = exp2f((float)dd * log2f(sig));
  }
  __syncthreads();

  int idx = blockIdx.x*256 + tid;
  if (idx >= NN) return;
  int i = idx / NTOK, j = idx % NTOK;
  float* Mout = M12 + (size_t)layer*MSZ + idx;
  if (i == 0 || j == 0){
#pragma unroll
    for (int h = 0; h < HEADS; ++h)
      Mout[(size_t)h*NN] = 1.0f;
  } else {
    int dv[NCURVES];
#pragma unroll
    for (int c = 0; c < NCURVES; ++c){
      int d = cis[c*NPATCH + (i-1)] - cis[c*NPATCH + (j-1)];
      dv[c] = d < 0 ? -d : d;
    }
#pragma unroll
    for (int h = 0; h < HEADS; ++h){
      float acc = 0.0f;
#pragma unroll
      for (int c = 0; c < NCURVES; ++c)
        acc += table[h][c][dv[c]];
      Mout[(size_t)h*NN] = acc * (1.0f/6.0f);
    }
  }
}

// ---------------- layernorm ----------------
template<int PAIR>
__global__ void layernorm_kernel(const float* __restrict__ in, long in_stride,
                                 const float* __restrict__ w, const float* __restrict__ b,
                                 float* __restrict__ outf,
                                 __half* __restrict__ oh, __half* __restrict__ ol){
  __shared__ float redS[8], redQ[8];
  __shared__ float s_mean, s_inv;
  int r = blockIdx.x;
  const float* xr = in + (long)r * in_stride;
  int tid = threadIdx.x, lane = tid & 31, wid = tid >> 5;

  float v0 = xr[tid], v1 = xr[tid+256], v2 = xr[tid+512];
  float s = v0 + v1 + v2;
  float q = v0*v0 + v1*v1 + v2*v2;
  s = warpSum(s); q = warpSum(q);
  if (lane == 0){ redS[wid] = s; redQ[wid] = q; }
  __syncthreads();
  if (tid == 0){
    float ts = 0.0f, tq = 0.0f;
#pragma unroll
    for (int i = 0; i < 8; ++i){ ts += redS[i]; tq += redQ[i]; }
    float mean = ts * (1.0f/CDIM);
    s_mean = mean;
    s_inv = rsqrtf(tq * (1.0f/CDIM) - mean*mean + 1e-5f);
  }
  __syncthreads();
  float mean = s_mean, inv = s_inv;
#pragma unroll
  for (int e = 0; e < 3; ++e){
    int c = tid + e*256;
    float xv = (e==0) ? v0 : (e==1) ? v1 : v2;
    float y = (xv - mean) * inv * w[c] + b[c];
    if (PAIR){
      split2h(y, &oh[(size_t)r*CDIM + c], &ol[(size_t)r*CDIM + c]);
    } else {
      outf[(size_t)r*CDIM + c] = y;
    }
  }
}

// ---------------- split-fp16 MMA GEMM: 128x128, 3-stage, warps 4(M)x2(N) ----------------
// Warp tile 32x64: A-fragment reuse 8 MMAs per ldmatrix (cuts smem read traffic 20%).
// EPI 0: fp32 store. 2: +bias +res -> fp32 store. 3: +bias, GELU -> fp16 pair.
// EPI 4: split-K partial -> atomicAdd into Cf (res pre-resident); bias by z==0.
template<int EPI>
__global__ void __launch_bounds__(256, 2)
mma_gemm_kernel(const __half* __restrict__ Ah_, const __half* __restrict__ Al_,
                const __half* __restrict__ Bh_,
                const float* __restrict__ bias, const float* __restrict__ res,
                float* __restrict__ Cf, __half* __restrict__ Ch, __half* __restrict__ Cl,
                int M, int N, int K, int Kchunk){
  extern __shared__ __align__(16) char dsm[];
  uint32_t sb = cvta_s(dsm);  // [3 stages][AH 8K | AL 8K | BH 8K]

  int tid = threadIdx.x, wid = tid >> 5, lane = tid & 31;
  int m0 = blockIdx.y * 128, n0 = blockIdx.x * 128;
  int kbase = blockIdx.z * Kchunk;
  int warp_m = wid & 3, warp_n = wid >> 2;   // 4 M-warps x 2 N-warps

  float acc[2][8][4];
#pragma unroll
  for (int a=0;a<2;++a)
#pragma unroll
    for (int b=0;b<8;++b)
#pragma unroll
      for (int c=0;c<4;++c) acc[a][b][c] = 0.0f;

  auto load_stage = [&](int it, int s){
    int k0 = kbase + it * 32;
    uint32_t st = sb + (uint32_t)s*24576u;
#pragma unroll
    for (int i = 0; i < 2; ++i){
      int c = i*256 + tid;
      int row = c >> 2, ch = c & 3;
      int gr = m0 + row;
      int ok = gr < M;
      cp_async16(st + swz(row,ch), Ah_ + (size_t)(ok?gr:0)*K + k0 + ch*8, ok?16:0);
    }
#pragma unroll
    for (int i = 0; i < 2; ++i){
      int c = i*256 + tid;
      int row = c >> 2, ch = c & 3;
      int gr = m0 + row;
      int ok = gr < M;
      cp_async16(st + 8192u + swz(row,ch), Al_ + (size_t)(ok?gr:0)*K + k0 + ch*8, ok?16:0);
    }
#pragma unroll
    for (int i = 0; i < 2; ++i){
      int c = i*256 + tid;
      int row = c >> 2, ch = c & 3;
      cp_async16(st + 16384u + swz(row,ch), Bh_ + (size_t)(n0+row)*K + k0 + ch*8, 16);
    }
  };

  int niter = Kchunk >> 5;
  load_stage(0, 0); CP_COMMIT();
  load_stage(1, 1); CP_COMMIT();

  int brow_b = warp_n*64 + (lane & 7) + ((lane >> 4) << 3);
  int bchp   = (lane >> 3) & 1;
  int arow_b = warp_m*32 + (lane & 15);
  int lau    = lane >> 4;

  for (int it = 0; it < niter; ++it){
    CP_WAIT(1);
    __syncthreads();
    if (it + 2 < niter) load_stage(it + 2, (it + 2) % 3);
    CP_COMMIT();

    int s = it % 3;
    uint32_t Abh = sb + (uint32_t)s*24576u;
    uint32_t Abl = Abh + 8192u;
    uint32_t Bbh = Abh + 16384u;

#pragma unroll
    for (int k16 = 0; k16 < 2; ++k16){
      uint32_t bf[4][4];   // 4 ldm_x4, each covers 2 n8 tiles
#pragma unroll
      for (int g = 0; g < 4; ++g)
        ldm_x4(bf[g], Bbh + swz(brow_b + g*16, k16*2 + bchp));
#pragma unroll
      for (int mt = 0; mt < 2; ++mt){
        uint32_t af[4];
        uint32_t aoff = swz(arow_b + mt*16, k16*2 + lau);
        ldm_x4(af, Abh + aoff);
#pragma unroll
        for (int g = 0; g < 4; ++g){
          mma16816(acc[mt][2*g+0], af, bf[g]+0);
          mma16816(acc[mt][2*g+1], af, bf[g]+2);
        }
        ldm_x4(af, Abl + aoff);
#pragma unroll
        for (int g = 0; g < 4; ++g){
          mma16816(acc[mt][2*g+0], af, bf[g]+0);
          mma16816(acc[mt][2*g+1], af, bf[g]+2);
        }
      }
    }
  }

  // epilogue
#pragma unroll
  for (int mt = 0; mt < 2; ++mt){
#pragma unroll
    for (int nt = 0; nt < 8; ++nt){
#pragma unroll
      for (int half = 0; half < 2; ++half){
        int gm = m0 + warp_m*32 + mt*16 + (lane >> 2) + half*8;
        if (gm >= M) continue;
#pragma unroll
        for (int e = 0; e < 2; ++e){
          int gn = n0 + warp_n*64 + nt*8 + 2*(lane & 3) + e;
          float v = acc[mt][nt][half*2 + e];
          if (EPI == 0){
            Cf[(size_t)gm*N + gn] = v;
          } else if (EPI == 2){
            v += bias[gn] + res[(size_t)gm*N + gn];
            Cf[(size_t)gm*N + gn] = v;
          } else if (EPI == 4){
            if (blockIdx.z == 0) v += bias[gn];
            atomicAdd(&Cf[(size_t)gm*N + gn], v);
          } else {
            v += bias[gn];
            float g = 0.5f * v * (1.0f + erff(v * 0.7071067811865475f));
            split2h(g, &Ch[(size_t)gm*N + gn], &Cl[(size_t)gm*N + gn]);
          }
        }
      }
    }
  }
}

// ---------------- attention: warp-per-row, 8 warps, ILP'd PV loop ----------------
__global__ void __launch_bounds__(256)
attention_kernel(const float* __restrict__ qkv, const float* __restrict__ M,
                 __half* __restrict__ oh, __half* __restrict__ ol){
  extern __shared__ float sm[];
  float* ks = sm;
  float* vs = ks + NTOK*KSTRIDE;
  float* qs = vs + NTOK*KSTRIDE;
  float* ps = qs + 8*68;

  int bh = blockIdx.x;
  int b = bh / HEADS, h = bh % HEADS;
  int tid = threadIdx.x, lane = tid & 31, wid = tid >> 5;
  const float scale = 0.125f;

  size_t base = (size_t)b * NTOK * 3 * CDIM;
  for (int idx = tid; idx < NTOK*16; idx += 256){
    int j = idx >> 4, d4 = idx & 15;
    float4 kv = *(const float4*)(qkv + base + (size_t)j*3*CDIM + CDIM   + h*HDIM + d4*4);
    float4 vv = *(const float4*)(qkv + base + (size_t)j*3*CDIM + 2*CDIM + h*HDIM + d4*4);
    *(float4*)(ks + j*KSTRIDE + d4*4) = kv;
    *(float4*)(vs + j*KSTRIDE + d4*4) = vv;
  }
  __syncthreads();

  const float* Mh = M + (size_t)h * NN;
  float* qw = qs + wid*68;
  float* pw = ps + wid*224;

  for (int i = wid; i < NTOK; i += 8){
    if (lane < 16)
      *(float4*)(qw + lane*4) = *(const float4*)(qkv + base + (size_t)i*3*CDIM + h*HDIM + lane*4);
    __syncwarp();

    float sj[7];
    float mx = -1e30f;
#pragma unroll
    for (int jj = 0; jj < 7; ++jj){
      int j = lane + jj*32;
      float acc = -1e30f;
      if (j < NTOK){
        const float4* k4 = (const float4*)(ks + j*KSTRIDE);
        const float4* q4 = (const float4*)qw;
        float a = 0.0f;
#pragma unroll
        for (int d4 = 0; d4 < 16; ++d4){
          float4 kv = k4[d4], qv = q4[d4];
          a += qv.x*kv.x + qv.y*kv.y + qv.z*kv.z + qv.w*kv.w;
        }
        acc = a * scale * Mh[(size_t)i*NTOK + j];
      }
      sj[jj] = acc;
      mx = fmaxf(mx, acc);
    }
    mx = warpMax(mx);
    float sum = 0.0f;
#pragma unroll
    for (int jj = 0; jj < 7; ++jj){
      int j = lane + jj*32;
      float p = (j < NTOK) ? __expf(sj[jj] - mx) : 0.0f;
      pw[j] = p;
      sum += p;
    }
    sum = warpSum(sum);
    float rinv = 1.0f / sum;
    __syncwarp();

    float a0 = 0.f, a1 = 0.f, b0 = 0.f, b1 = 0.f;
    float c0 = 0.f, c1 = 0.f, d0 = 0.f, d1 = 0.f;
    int j = 0;
    for (; j + 4 <= 196; j += 4){
      float p0 = pw[j], p1 = pw[j+1], p2 = pw[j+2], p3 = pw[j+3];
      float2 v0 = *(const float2*)(vs + (j  )*KSTRIDE + lane*2);
      float2 v1 = *(const float2*)(vs + (j+1)*KSTRIDE + lane*2);
      float2 v2 = *(const float2*)(vs + (j+2)*KSTRIDE + lane*2);
      float2 v3 = *(const float2*)(vs + (j+3)*KSTRIDE + lane*2);
      a0 += p0*v0.x; a1 += p0*v0.y;
      b0 += p1*v1.x; b1 += p1*v1.y;
      c0 += p2*v2.x; c1 += p2*v2.y;
      d0 += p3*v3.x; d1 += p3*v3.y;
    }
    {
      float p = pw[196];
      float2 vv = *(const float2*)(vs + 196*KSTRIDE + lane*2);
      a0 += p*vv.x; a1 += p*vv.y;
    }
    float o0 = ((a0 + b0) + (c0 + d0)) * rinv;
    float o1 = ((a1 + b1) + (c1 + d1)) * rinv;
    size_t oidx = ((size_t)(b*NTOK + i))*CDIM + h*HDIM + lane*2;
    split2h(o0, &oh[oidx],   &ol[oidx]);
    split2h(o1, &oh[oidx+1], &ol[oidx+1]);
    __syncwarp();
  }
}

// ---------------- classifier head ----------------
__global__ void head_kernel(const float* __restrict__ cls, const float* __restrict__ W,
                            const float* __restrict__ bias, float* __restrict__ out){
  __shared__ float cs[CDIM];
  int b = blockIdx.y;
  int n = blockIdx.x*256 + threadIdx.x;
  for (int k = threadIdx.x; k < CDIM; k += 256) cs[k] = cls[b*CDIM + k];
  __syncthreads();
  if (n < NCLS){
    float acc = bias[n];
#pragma unroll 4
    for (int k = 0; k < CDIM; ++k)
      acc += cs[k] * W[(size_t)k*NCLS + n];
    out[b*NCLS + n] = acc;
  }
}

// ---------------- launcher ----------------
extern "C" void kernel_launch(void* const* d_in, const int* in_sizes, int n_in,
                              void* d_out, int out_size){
  (void)in_sizes; (void)n_in; (void)out_size;
  const float* images  = (const float*)d_in[0];
  const float* patch_w = (const float*)d_in[1];
  const float* patch_b = (const float*)d_in[2];
  const float* cls_tok = (const float*)d_in[3];
  const float* pos_emb = (const float*)d_in[4];
  const float* ln1_w   = (const float*)d_in[5];
  const float* ln1_b   = (const float*)d_in[6];
  const float* qkv_w   = (const float*)d_in[7];
  const float* proj_w  = (const float*)d_in[8];
  const float* proj_b  = (const float*)d_in[9];
  const float* ai      = (const float*)d_in[10];
  const float* ln2_w   = (const float*)d_in[11];
  const float* ln2_b   = (const float*)d_in[12];
  const float* fc1_w   = (const float*)d_in[13];
  const float* fc1_b   = (const float*)d_in[14];
  const float* fc2_w   = (const float*)d_in[15];
  const float* fc2_b   = (const float*)d_in[16];
  const float* norm_w  = (const float*)d_in[17];
  const float* norm_b  = (const float*)d_in[18];
  const float* head_w  = (const float*)d_in[19];
  const float* head_b  = (const float*)d_in[20];
  const int*   curve   = (const int*)d_in[21];
  float* out = (float*)d_out;

  __half *wh,*hh,*hl,*oh,*ol,*h2h,*h2l,*pah,*pal;
  float *x,*qkvb,*Mb,*pt,*cls;
  cudaGetSymbolAddress((void**)&wh,  g_wh);
  cudaGetSymbolAddress((void**)&hh,  g_hh);
  cudaGetSymbolAddress((void**)&hl,  g_hl);
  cudaGetSymbolAddress((void**)&oh,  g_oh);
  cudaGetSymbolAddress((void**)&ol,  g_ol);
  cudaGetSymbolAddress((void**)&h2h, g_h2h);
  cudaGetSymbolAddress((void**)&h2l, g_h2l);
  cudaGetSymbolAddress((void**)&pah, g_pah);
  cudaGetSymbolAddress((void**)&pal, g_pal);
  cudaGetSymbolAddress((void**)&x,   g_x);
  cudaGetSymbolAddress((void**)&qkvb,g_qkv);
  cudaGetSymbolAddress((void**)&Mb,  g_M);
  cudaGetSymbolAddress((void**)&pt,  g_pt);
  cudaGetSymbolAddress((void**)&cls, g_cls);

  const int attSmem = (2*NTOK*KSTRIDE + 8*68 + 8*224) * (int)sizeof(float);
  cudaFuncSetAttribute(attention_kernel, cudaFuncAttributeMaxDynamicSharedMemorySize, attSmem);
  const int gemmSmem = 73728;  // 3 stages x 24KB
  cudaFuncSetAttribute(mma_gemm_kernel<0>, cudaFuncAttributeMaxDynamicSharedMemorySize, gemmSmem);
  cudaFuncSetAttribute(mma_gemm_kernel<2>, cudaFuncAttributeMaxDynamicSharedMemorySize, gemmSmem);
  cudaFuncSetAttribute(mma_gemm_kernel<3>, cudaFuncAttributeMaxDynamicSharedMemorySize, gemmSmem);
  cudaFuncSetAttribute(mma_gemm_kernel<4>, cudaFuncAttributeMaxDynamicSharedMemorySize, gemmSmem);

  dim3 tb(32, 8);
  const int mt = (ROWS + 127)/128;   // 50
  const int pmt = (PROWS + 127)/128; // 49

  // ---- ordered so launch #6 (ncu -s 5 -c 1) is the layer-0 QKV GEMM ----
  im2col_kernel<<<(PROWS*CDIM+255)/256, 256>>>(images, pah, pal);                         // 1
  split_pw_kernel<<<(CDIM*CDIM+255)/256, 256>>>(patch_w, wh + OFF_PATCH);                 // 2
  tsplit_kernel<<<dim3(2304/32, 768/32, DEPTH), tb>>>(qkv_w,  wh + OFF_QKV,  768, 2304);  // 3
  mma_gemm_kernel<0><<<dim3(768/128, pmt), 256, gemmSmem>>>(                              // 4
      pah, pal, wh + OFF_PATCH,
      nullptr, nullptr, pt, nullptr, nullptr, PROWS, 768, 768, 768);
  assemble_ln_kernel<<<ROWS, 256>>>(pt, cls_tok, pos_emb, patch_b, ln1_w, ln1_b, x, hh, hl); // 5
  mma_gemm_kernel<0><<<dim3(2304/128, mt), 256, gemmSmem>>>(                              // 6 <- profiled
      hh, hl, wh + OFF_QKV,
      nullptr, nullptr, qkvb, nullptr, nullptr, ROWS, 2304, 768, 768);
  tsplit_kernel<<<dim3(768/32,  768/32, DEPTH), tb>>>(proj_w, wh + OFF_PROJ, 768, 768);   // 7
  tsplit_kernel<<<dim3(3072/32, 768/32, DEPTH), tb>>>(fc1_w,  wh + OFF_FC1,  768, 3072);  // 8
  tsplit_kernel<<<dim3(768/32, 3072/32, DEPTH), tb>>>(fc2_w,  wh + OFF_FC2,  3072, 768);  // 9
  compute_M_kernel<<<dim3((NN+255)/256, 1, DEPTH), 256>>>(ai, curve, Mb);                 // 10

  for (int d = 0; d < DEPTH; ++d){
    if (d > 0){
      layernorm_kernel<1><<<ROWS, 256>>>(x, CDIM, ln1_w + d*CDIM, ln1_b + d*CDIM, nullptr, hh, hl);
      mma_gemm_kernel<0><<<dim3(2304/128, mt), 256, gemmSmem>>>(
          hh, hl, wh + OFF_QKV + (size_t)d*QKV_T,
          nullptr, nullptr, qkvb, nullptr, nullptr, ROWS, 2304, 768, 768);
    }
    attention_kernel<<<BATCH*HEADS, 256, attSmem>>>(qkvb, Mb + (size_t)d*MSZ, oh, ol);
    mma_gemm_kernel<4><<<dim3(768/128, mt, 2), 256, gemmSmem>>>(
        oh, ol, wh + OFF_PROJ + (size_t)d*PROJ_T,
        proj_b + d*CDIM, nullptr, x, nullptr, nullptr, ROWS, 768, 768, 384);
    layernorm_kernel<1><<<ROWS, 256>>>(x, CDIM, ln2_w + d*CDIM, ln2_b + d*CDIM, nullptr, hh, hl);
    mma_gemm_kernel<3><<<dim3(3072/128, mt), 256, gemmSmem>>>(
        hh, hl, wh + OFF_FC1 + (size_t)d*FC1_T,
        fc1_b + d*HID, nullptr, nullptr, h2h, h2l, ROWS, 3072, 768, 768);
    mma_gemm_kernel<4><<<dim3(768/128, mt, 4), 256, gemmSmem>>>(
        h2h, h2l, wh + OFF_FC2 + (size_t)d*FC2_T,
        fc2_b + d*CDIM, nullptr, x, nullptr, nullptr, ROWS, 768, 3072, 768);
  }

  layernorm_kernel<0><<<BATCH, 256>>>(x, (long)NTOK*CDIM, norm_w, norm_b, cls, nullptr, nullptr);
  head_kernel<<<dim3(4, BATCH), 256>>>(cls, head_w, head_b, out);
}